// round 13
// baseline (speedup 1.0000x reference)
#include <cuda_runtime.h>
#include <cuda_bf16.h>
#include <math_constants.h>
#include <cstdint>

// Problem constants
#define Bz     4
#define C_IN   192
#define Nn     4096
#define BN     (Bz * Nn)          // 16384 nodes
#define E_CNT  262144             // edges
#define C_OUT  384
#define K2     (2 * C_IN)         // 384  (combined GEMM K)
#define CAP    64                 // per-node bucket capacity

// ---------------- scratch (static device globals; no allocation) ----------------
__device__ __align__(16) float g_xt[BN * C_IN];             // node-major fp32 x (agg gather)
__device__ __align__(16) __nv_bfloat16 g_bx_hi[BN * C_IN];  // x  node-major bf16 hi
__device__ __align__(16) __nv_bfloat16 g_bx_lo[BN * C_IN];  // x  node-major bf16 lo
__device__ __align__(16) __nv_bfloat16 g_bg_hi[BN * C_IN];  // agg node-major bf16 hi
__device__ __align__(16) __nv_bfloat16 g_bg_lo[BN * C_IN];  // agg node-major bf16 lo
__device__ __align__(16) __nv_bfloat16 g_a_hi[C_OUT * K2];  // A=[Wx|Wg] K-major bf16 hi
__device__ __align__(16) __nv_bfloat16 g_a_lo[C_OUT * K2];  // A lo
__device__ int   g_cnt[BN];
__device__ int   g_bucket[BN * CAP];     // fixed-stride buckets (4 MB)
__device__ int   g_ovsrc[E_CNT];         // overflow spill (exactness guarantee)
__device__ int   g_ovdst[E_CNT];
__device__ int   g_ovcnt;
__device__ int   g_is64;                 // edge dtype flag (1 = int64, 0 = int32)

// ---------------- helpers ----------------
__device__ __forceinline__ uint32_t smem_u32(const void* p) {
    uint32_t a;
    asm("{ .reg .u64 t; cvta.to.shared.u64 t, %1; cvt.u32.u64 %0, t; }" : "=r"(a) : "l"(p));
    return a;
}

__device__ __forceinline__ void ldsm_x4(uint32_t addr, uint32_t& r0, uint32_t& r1,
                                        uint32_t& r2, uint32_t& r3) {
    asm volatile("ldmatrix.sync.aligned.m8n8.x4.shared.b16 {%0,%1,%2,%3}, [%4];"
                 : "=r"(r0), "=r"(r1), "=r"(r2), "=r"(r3) : "r"(addr));
}

__device__ __forceinline__ void mma_bf16(float& c0, float& c1, float& c2, float& c3,
                                         uint32_t a0, uint32_t a1, uint32_t a2, uint32_t a3,
                                         uint32_t b0, uint32_t b1) {
    asm volatile(
        "mma.sync.aligned.m16n8k16.row.col.f32.bf16.bf16.f32 "
        "{%0,%1,%2,%3}, {%4,%5,%6,%7}, {%8,%9}, {%0,%1,%2,%3};"
        : "+f"(c0), "+f"(c1), "+f"(c2), "+f"(c3)
        : "r"(a0), "r"(a1), "r"(a2), "r"(a3), "r"(b0), "r"(b1));
}

__device__ __forceinline__ void cp_async16(uint32_t smem, const void* gptr) {
    asm volatile("cp.async.cg.shared.global [%0], [%1], 16;" :: "r"(smem), "l"(gptr));
}

__device__ __forceinline__ int load_edge(const void* ei, int idx) {
    if (g_is64) return (int)((const long long*)ei)[idx];
    return ((const int*)ei)[idx];
}

__device__ __forceinline__ void split_bf16(float v, __nv_bfloat16& hi, __nv_bfloat16& lo) {
    hi = __float2bfloat16(v);
    lo = __float2bfloat16(v - __bfloat162float(hi));
}

__device__ __forceinline__ float4 max4(float4 a, float4 b) {
    float4 r;
    r.x = fmaxf(a.x, b.x); r.y = fmaxf(a.y, b.y);
    r.z = fmaxf(a.z, b.z); r.w = fmaxf(a.w, b.w);
    return r;
}

// split a float4 into packed-bf16 hi/lo uint2s
__device__ __forceinline__ void split4(float4 v, uint2& hi, uint2& lo) {
    __nv_bfloat16 h0, h1, h2, h3, l0, l1, l2, l3;
    split_bf16(v.x, h0, l0); split_bf16(v.y, h1, l1);
    split_bf16(v.z, h2, l2); split_bf16(v.w, h3, l3);
    hi.x = (uint32_t)*(uint16_t*)&h0 | ((uint32_t)*(uint16_t*)&h1 << 16);
    hi.y = (uint32_t)*(uint16_t*)&h2 | ((uint32_t)*(uint16_t*)&h3 << 16);
    lo.x = (uint32_t)*(uint16_t*)&l0 | ((uint32_t)*(uint16_t*)&l1 << 16);
    lo.y = (uint32_t)*(uint16_t*)&l2 | ((uint32_t)*(uint16_t*)&l3 << 16);
}

// ---------------- merged prep: probe + zero counts + W deinterleave/split ------
__global__ void prep_kernel(const void* __restrict__ ei, const float* __restrict__ W) {
    int blk = blockIdx.x;
    int t   = threadIdx.x;
    if (blk == 0) {
        if (t == 0) { g_is64 = 1; g_ovcnt = 0; }
        __threadfence();
        const long long* p = (const long long*)ei;
        long long v = p[t];
        if (v < 0 || v >= BN) atomicExch(&g_is64, 0);
    } else if (blk <= 64) {
        g_cnt[(blk - 1) * 256 + t] = 0;
    } else {
        int i = (blk - 65) * 256 + t;            // over C_OUT*K2
        int o = i / K2, k = i % K2;
        float v = (k < C_IN) ? W[o * K2 + 2 * k] : W[o * K2 + 2 * (k - C_IN) + 1];
        __nv_bfloat16 hi, lo;
        split_bf16(v, hi, lo);
        g_a_hi[i] = hi;
        g_a_lo[i] = lo;
    }
}

// ---------------- fused transpose + scatter ----------------
// blocks 0..1023    : edge scatter into fixed-capacity buckets
// blocks 1024..4095 : x (B,C,N) -> node-major fp32 + bf16 hi/lo (32x32 tiles)
__global__ void transpose_scatter_kernel(const float* __restrict__ x,
                                         const void* __restrict__ ei) {
    __shared__ float tile[32][33];
    int blk = blockIdx.x;
    int tid = threadIdx.x;

    if (blk < 1024) {
        int e = blk * 256 + tid;
        int d = load_edge(ei, e);
        int s = load_edge(ei, E_CNT + e);
        if ((unsigned)d < BN && (unsigned)s < BN) {
            int pos = atomicAdd(&g_cnt[d], 1);
            if (pos < CAP) {
                g_bucket[d * CAP + pos] = s;
            } else {                              // exact spill path (≈never)
                int op = atomicAdd(&g_ovcnt, 1);
                if (op < E_CNT) { g_ovsrc[op] = s; g_ovdst[op] = d; }
            }
        }
        return;
    }

    int q  = blk - 1024;                 // 0..3071
    int n0 = (q & 127) * 32;             // 128 n-tiles
    int c0 = ((q >> 7) % 6) * 32;        // 6 c-tiles
    int b  = q / (128 * 6);              // 4 batches
    int tx = tid & 31, ty = tid >> 5;    // 32 x 8
    #pragma unroll
    for (int i = 0; i < 4; ++i) {
        int c = c0 + ty + 8 * i;
        tile[ty + 8 * i][tx] = x[((size_t)b * C_IN + c) * Nn + n0 + tx];
    }
    __syncthreads();
    #pragma unroll
    for (int i = 0; i < 4; ++i) {
        int n = n0 + ty + 8 * i;
        size_t idx = ((size_t)b * Nn + n) * C_IN + c0 + tx;
        float v = tile[tx][ty + 8 * i];
        g_xt[idx] = v;
        __nv_bfloat16 hi, lo;
        split_bf16(v, hi, lo);
        g_bx_hi[idx] = hi;
        g_bx_lo[idx] = lo;
    }
}

// ---------------- aggregation: one warp per node, float4 gathers ----------------
__global__ void agg_kernel() {
    int gtid = blockIdx.x * blockDim.x + threadIdx.x;
    int node = gtid >> 5;
    int lane = threadIdx.x & 31;
    if (node >= BN) return;
    int deg = g_cnt[node];
    int nb  = deg < CAP ? deg : CAP;
    bool lo16 = lane < 16;

    const float4 NEG4 = make_float4(-CUDART_INF_F, -CUDART_INF_F, -CUDART_INF_F, -CUDART_INF_F);
    float4 ma = NEG4, mb = NEG4;

    const int* brow = g_bucket + node * CAP;
    int my_src = (lane < nb) ? brow[lane] : 0;
    int cnt = nb < 32 ? nb : 32;

    int i = 0;
    for (; i + 4 <= cnt; i += 4) {       // 4 neighbors in flight, float4-wide
        int s0 = __shfl_sync(0xFFFFFFFFu, my_src, i);
        int s1 = __shfl_sync(0xFFFFFFFFu, my_src, i + 1);
        int s2 = __shfl_sync(0xFFFFFFFFu, my_src, i + 2);
        int s3 = __shfl_sync(0xFFFFFFFFu, my_src, i + 3);
        const float4* r0 = (const float4*)(g_xt + (size_t)s0 * C_IN);
        const float4* r1 = (const float4*)(g_xt + (size_t)s1 * C_IN);
        const float4* r2 = (const float4*)(g_xt + (size_t)s2 * C_IN);
        const float4* r3 = (const float4*)(g_xt + (size_t)s3 * C_IN);
        float4 a0 = r0[lane], a1 = r1[lane], a2 = r2[lane], a3 = r3[lane];
        if (lo16) {
            float4 b0 = r0[32 + lane], b1 = r1[32 + lane];
            float4 b2 = r2[32 + lane], b3 = r3[32 + lane];
            mb = max4(mb, max4(max4(b0, b1), max4(b2, b3)));
        }
        ma = max4(ma, max4(max4(a0, a1), max4(a2, a3)));
    }
    for (; i < cnt; ++i) {
        int s0 = __shfl_sync(0xFFFFFFFFu, my_src, i);
        const float4* r0 = (const float4*)(g_xt + (size_t)s0 * C_IN);
        ma = max4(ma, r0[lane]);
        if (lo16) mb = max4(mb, r0[32 + lane]);
    }
    for (int e = 32; e < nb; ++e) {
        int s = brow[e];
        const float4* r = (const float4*)(g_xt + (size_t)s * C_IN);
        ma = max4(ma, r[lane]);
        if (lo16) mb = max4(mb, r[32 + lane]);
    }
    int nov = g_ovcnt;
    if (nov > E_CNT) nov = E_CNT;
    for (int e = 0; e < nov; ++e) {
        if (g_ovdst[e] == node) {
            const float4* r = (const float4*)(g_xt + (size_t)g_ovsrc[e] * C_IN);
            ma = max4(ma, r[lane]);
            if (lo16) mb = max4(mb, r[32 + lane]);
        }
    }

    const float4* xr = (const float4*)(g_xt + (size_t)node * C_IN);
    bool has = deg > 0;
    {
        float4 xa = xr[lane];
        float4 va = has ? make_float4(ma.x - xa.x, ma.y - xa.y, ma.z - xa.z, ma.w - xa.w)
                        : make_float4(0.f, 0.f, 0.f, 0.f);
        uint2 hi, lo;
        split4(va, hi, lo);
        size_t idx = (size_t)node * C_IN + lane * 4;
        *(uint2*)((char*)g_bg_hi + idx * 2) = hi;
        *(uint2*)((char*)g_bg_lo + idx * 2) = lo;
    }
    if (lo16) {
        float4 xb = xr[32 + lane];
        float4 vb = has ? make_float4(mb.x - xb.x, mb.y - xb.y, mb.z - xb.z, mb.w - xb.w)
                        : make_float4(0.f, 0.f, 0.f, 0.f);
        uint2 hi, lo;
        split4(vb, hi, lo);
        size_t idx = (size_t)node * C_IN + 128 + lane * 4;
        *(uint2*)((char*)g_bg_hi + idx * 2) = hi;
        *(uint2*)((char*)g_bg_lo + idx * 2) = lo;
    }
}

// ---------------- HMMA GEMM (double-buffered cp.async, 512 threads) ----------
// 3-term bf16 split: D = A_hi*B_hi + A_hi*B_lo + A_lo*B_hi (fp32 reg accum).
// CTA tile 128(M) x 64(N); 16 warps = 4(M) x 4(N), warp tile 32 x 16.
// Doubled warps/SM (32 at 2 CTAs/SM) to fill the 52% tensor-pipe idle seen
// at 16 warps/SM (R8/R12 both pinned at tensor=47.8%).
// 12 K-chunks of 32 bf16. Stage = Ah,Al (128x80B) + Bh,Bl (64x80B) = 30720B;
// 2 stages = 61440B (same proven footprint as R12).
// Pitch 80B = 20-bank stride -> ldmatrix conflict-free.

#define PITCH_B 80
#define A_ROWS 128
#define B_ROWS 64
#define A_GRANULES (A_ROWS * 4)         // 512 data granules
#define B_GRANULES (B_ROWS * 4)         // 256 data granules
#define OFF_AH 0
#define OFF_AL (A_ROWS * PITCH_B)                   // 10240
#define OFF_BH (2 * A_ROWS * PITCH_B)               // 20480
#define OFF_BL (2 * A_ROWS * PITCH_B + B_ROWS * PITCH_B)  // 25600
#define STAGE_BYTES (2 * A_ROWS * PITCH_B + 2 * B_ROWS * PITCH_B)  // 30720
#define GEMM_SMEM (2 * STAGE_BYTES)                 // 61440
#define NCHUNK 12
#define GTHREADS 512

extern __shared__ __align__(16) char g_dsm[];

__global__ __launch_bounds__(GTHREADS, 2) void hmma_gemm_kernel(
    const float* __restrict__ bias, float* __restrict__ out)
{
    int tid  = threadIdx.x;
    int wid  = tid >> 5;        // 0..15
    int lane = tid & 31;
    int wm   = wid & 3;         // warp row 0..3  -> m offset wm*32
    int wn   = wid >> 2;        // warp col 0..3  -> n offset wn*16
    int n0 = blockIdx.x * 64;
    int m0 = blockIdx.y * 128;
    int bb = blockIdx.z;

    uint32_t dsm = smem_u32(g_dsm);
    int row_in = lane & 7;
    int sub    = lane >> 3;      // 0..3
    int node0  = bb * Nn + n0;

    const char* a_hi = (const char*)g_a_hi;
    const char* a_lo = (const char*)g_a_lo;

    auto load_stage = [&](int stage, int cc) {     // cc = 0..11
        const char* bh_src = (cc < 6) ? (const char*)g_bx_hi : (const char*)g_bg_hi;
        const char* bl_src = (cc < 6) ? (const char*)g_bx_lo : (const char*)g_bg_lo;
        int kkA = cc * 32;                          // A K-offset (bf16 elements)
        int kkB = (cc % 6) * 32;                    // B K-offset within its source
        uint32_t st = dsm + stage * STAGE_BYTES;
        if (tid < A_GRANULES) {                     // 512 data granules, 1/thread
            int row = tid >> 2, q = tid & 3;
            size_t a_off = (size_t)(m0 + row) * (K2 * 2) + kkA * 2 + q * 16;
            uint32_t so = row * PITCH_B + q * 16;
            cp_async16(st + OFF_AH + so, a_hi + a_off);
            cp_async16(st + OFF_AL + so, a_lo + a_off);
        }
        if (tid < B_GRANULES) {                     // 256 data granules
            int row = tid >> 2, q = tid & 3;
            size_t b_off = (size_t)(node0 + row) * (C_IN * 2) + kkB * 2 + q * 16;
            uint32_t so = row * PITCH_B + q * 16;
            cp_async16(st + OFF_BH + so, bh_src + b_off);
            cp_async16(st + OFF_BL + so, bl_src + b_off);
        }
    };

    float acc[2][2][4];
    #pragma unroll
    for (int i = 0; i < 2; ++i)
        #pragma unroll
        for (int j = 0; j < 2; ++j)
            #pragma unroll
            for (int r = 0; r < 4; ++r) acc[i][j][r] = 0.0f;

    load_stage(0, 0);
    asm volatile("cp.async.commit_group;" ::: "memory");

    for (int cc = 0; cc < NCHUNK; ++cc) {
        if (cc < NCHUNK - 1) {
            load_stage((cc + 1) & 1, cc + 1);
            asm volatile("cp.async.commit_group;" ::: "memory");
            asm volatile("cp.async.wait_group 1;" ::: "memory");
        } else {
            asm volatile("cp.async.wait_group 0;" ::: "memory");
        }
        __syncthreads();

        uint32_t st = dsm + (cc & 1) * STAGE_BYTES;
        #pragma unroll
        for (int ks = 0; ks < 2; ++ks) {
            int k0 = ks * 16;
            uint32_t a_row_off  = (wm * 32 + row_in + (sub & 1) * 8) * PITCH_B
                                  + (k0 + (sub >> 1) * 8) * 2;
            uint32_t b_lane_off = (wn * 16 + (sub >> 1) * 8 + row_in) * PITCH_B
                                  + (k0 + (sub & 1) * 8) * 2;

            uint32_t ah[2][4], al[2][4];
            #pragma unroll
            for (int f = 0; f < 2; ++f)
                ldsm_x4(st + OFF_AH + a_row_off + f * 16 * PITCH_B,
                        ah[f][0], ah[f][1], ah[f][2], ah[f][3]);

            uint32_t bf[2][2];
            {
                uint32_t r0, r1, r2, r3;
                ldsm_x4(st + OFF_BH + b_lane_off, r0, r1, r2, r3);
                bf[0][0] = r0; bf[0][1] = r1;
                bf[1][0] = r2; bf[1][1] = r3;
            }
            // hi * hi
            #pragma unroll
            for (int mi = 0; mi < 2; ++mi)
                #pragma unroll
                for (int nj = 0; nj < 2; ++nj)
                    mma_bf16(acc[mi][nj][0], acc[mi][nj][1], acc[mi][nj][2], acc[mi][nj][3],
                             ah[mi][0], ah[mi][1], ah[mi][2], ah[mi][3],
                             bf[nj][0], bf[nj][1]);
            // lo * hi
            #pragma unroll
            for (int f = 0; f < 2; ++f)
                ldsm_x4(st + OFF_AL + a_row_off + f * 16 * PITCH_B,
                        al[f][0], al[f][1], al[f][2], al[f][3]);
            #pragma unroll
            for (int mi = 0; mi < 2; ++mi)
                #pragma unroll
                for (int nj = 0; nj < 2; ++nj)
                    mma_bf16(acc[mi][nj][0], acc[mi][nj][1], acc[mi][nj][2], acc[mi][nj][3],
                             al[mi][0], al[mi][1], al[mi][2], al[mi][3],
                             bf[nj][0], bf[nj][1]);
            // hi * lo (reload bf with B_lo)
            {
                uint32_t r0, r1, r2, r3;
                ldsm_x4(st + OFF_BL + b_lane_off, r0, r1, r2, r3);
                bf[0][0] = r0; bf[0][1] = r1;
                bf[1][0] = r2; bf[1][1] = r3;
            }
            #pragma unroll
            for (int mi = 0; mi < 2; ++mi)
                #pragma unroll
                for (int nj = 0; nj < 2; ++nj)
                    mma_bf16(acc[mi][nj][0], acc[mi][nj][1], acc[mi][nj][2], acc[mi][nj][3],
                             ah[mi][0], ah[mi][1], ah[mi][2], ah[mi][3],
                             bf[nj][0], bf[nj][1]);
        }
        __syncthreads();
    }

    // epilogue: bias + relu
    int g  = lane >> 2;        // 0..7
    int tq = lane & 3;         // 0..3
    #pragma unroll
    for (int mi = 0; mi < 2; ++mi) {
        int r0 = m0 + wm * 32 + mi * 16 + g;
        int r1 = r0 + 8;
        float bv0 = bias[r0];
        float bv1 = bias[r1];
        float* o0 = out + ((size_t)bb * C_OUT + r0) * Nn + n0 + wn * 16 + tq * 2;
        float* o1 = out + ((size_t)bb * C_OUT + r1) * Nn + n0 + wn * 16 + tq * 2;
        #pragma unroll
        for (int nj = 0; nj < 2; ++nj) {
            float2 v0, v1;
            v0.x = fmaxf(acc[mi][nj][0] + bv0, 0.0f);
            v0.y = fmaxf(acc[mi][nj][1] + bv0, 0.0f);
            v1.x = fmaxf(acc[mi][nj][2] + bv1, 0.0f);
            v1.y = fmaxf(acc[mi][nj][3] + bv1, 0.0f);
            *(float2*)(o0 + nj * 8) = v0;
            *(float2*)(o1 + nj * 8) = v1;
        }
    }
}

// ---------------- launcher ----------------
extern "C" void kernel_launch(void* const* d_in, const int* in_sizes, int n_in,
                              void* d_out, int out_size) {
    const float* x  = (const float*)d_in[0];       // (4,192,4096,1)
    const void*  ei = (const void*)d_in[1];        // (2, 262144) int32 or int64
    const float* W  = (const float*)d_in[2];       // (384, 384)
    const float* bv = (const float*)d_in[3];       // (384,)
    float* out = (float*)d_out;                    // (4,384,4096,1)

    cudaFuncSetAttribute(hmma_gemm_kernel,
                         cudaFuncAttributeMaxDynamicSharedMemorySize, GEMM_SMEM);

    prep_kernel<<<641, 256>>>(ei, W);                                   // 1
    transpose_scatter_kernel<<<4096, 256>>>(x, ei);                     // 2
    agg_kernel<<<(BN * 32) / 256, 256>>>();                             // 3
    hmma_gemm_kernel<<<dim3(Nn / 64, C_OUT / 128, Bz), GTHREADS, GEMM_SMEM>>>(bv, out); // 4
}

// round 14
// speedup vs baseline: 1.2559x; 1.2559x over previous
#include <cuda_runtime.h>
#include <cuda_fp16.h>
#include <math_constants.h>
#include <cstdint>

// Problem constants
#define Bz     4
#define C_IN   192
#define Nn     4096
#define BN     (Bz * Nn)          // 16384 nodes
#define E_CNT  262144             // edges
#define C_OUT  384
#define K2     (2 * C_IN)         // 384  (combined GEMM K)
#define CAP    64                 // per-node bucket capacity

// ---------------- scratch (static device globals; no allocation) ----------------
__device__ __align__(16) float g_xt[BN * C_IN];        // node-major fp32 x (agg gather)
__device__ __align__(16) __half g_bx_h[BN * C_IN];     // x   node-major fp16
__device__ __align__(16) __half g_bg_h[BN * C_IN];     // agg node-major fp16
__device__ __align__(16) __half g_a_hi[C_OUT * K2];    // A=[Wx|Wg] K-major fp16 hi
__device__ __align__(16) __half g_a_lo[C_OUT * K2];    // A lo (fp16 residual)
__device__ int   g_cnt[BN];
__device__ int   g_bucket[BN * CAP];     // fixed-stride buckets (4 MB)
__device__ int   g_ovsrc[E_CNT];         // overflow spill (exactness guarantee)
__device__ int   g_ovdst[E_CNT];
__device__ int   g_ovcnt;
__device__ int   g_is64;                 // edge dtype flag (1 = int64, 0 = int32)

// ---------------- helpers ----------------
__device__ __forceinline__ uint32_t smem_u32(const void* p) {
    uint32_t a;
    asm("{ .reg .u64 t; cvta.to.shared.u64 t, %1; cvt.u32.u64 %0, t; }" : "=r"(a) : "l"(p));
    return a;
}

__device__ __forceinline__ void ldsm_x4(uint32_t addr, uint32_t& r0, uint32_t& r1,
                                        uint32_t& r2, uint32_t& r3) {
    asm volatile("ldmatrix.sync.aligned.m8n8.x4.shared.b16 {%0,%1,%2,%3}, [%4];"
                 : "=r"(r0), "=r"(r1), "=r"(r2), "=r"(r3) : "r"(addr));
}

__device__ __forceinline__ void mma_f16(float& c0, float& c1, float& c2, float& c3,
                                        uint32_t a0, uint32_t a1, uint32_t a2, uint32_t a3,
                                        uint32_t b0, uint32_t b1) {
    asm volatile(
        "mma.sync.aligned.m16n8k16.row.col.f32.f16.f16.f32 "
        "{%0,%1,%2,%3}, {%4,%5,%6,%7}, {%8,%9}, {%0,%1,%2,%3};"
        : "+f"(c0), "+f"(c1), "+f"(c2), "+f"(c3)
        : "r"(a0), "r"(a1), "r"(a2), "r"(a3), "r"(b0), "r"(b1));
}

__device__ __forceinline__ int load_edge(const void* ei, int idx) {
    if (g_is64) return (int)((const long long*)ei)[idx];
    return ((const int*)ei)[idx];
}

__device__ __forceinline__ float4 max4(float4 a, float4 b) {
    float4 r;
    r.x = fmaxf(a.x, b.x); r.y = fmaxf(a.y, b.y);
    r.z = fmaxf(a.z, b.z); r.w = fmaxf(a.w, b.w);
    return r;
}

// pack a float4 into 4 fp16 (uint2)
__device__ __forceinline__ uint2 pack_h4(float4 v) {
    __half2 h01 = __floats2half2_rn(v.x, v.y);
    __half2 h23 = __floats2half2_rn(v.z, v.w);
    uint2 r;
    r.x = *(uint32_t*)&h01;
    r.y = *(uint32_t*)&h23;
    return r;
}

// ---------------- merged prep: probe + zero counts + W deinterleave/split ------
__global__ void prep_kernel(const void* __restrict__ ei, const float* __restrict__ W) {
    int blk = blockIdx.x;
    int t   = threadIdx.x;
    if (blk == 0) {
        if (t == 0) { g_is64 = 1; g_ovcnt = 0; }
        __threadfence();
        const long long* p = (const long long*)ei;
        long long v = p[t];
        if (v < 0 || v >= BN) atomicExch(&g_is64, 0);
    } else if (blk <= 64) {
        g_cnt[(blk - 1) * 256 + t] = 0;
    } else {
        int i = (blk - 65) * 256 + t;            // over C_OUT*K2
        int o = i / K2, k = i % K2;
        float v = (k < C_IN) ? W[o * K2 + 2 * k] : W[o * K2 + 2 * (k - C_IN) + 1];
        __half hi = __float2half_rn(v);
        __half lo = __float2half_rn(v - __half2float(hi));
        g_a_hi[i] = hi;
        g_a_lo[i] = lo;
    }
}

// ---------------- fused transpose + scatter ----------------
// blocks 0..1023    : edge scatter into fixed-capacity buckets
// blocks 1024..4095 : x (B,C,N) -> node-major fp32 + fp16 (32x32 tiles)
__global__ void transpose_scatter_kernel(const float* __restrict__ x,
                                         const void* __restrict__ ei) {
    __shared__ float tile[32][33];
    int blk = blockIdx.x;
    int tid = threadIdx.x;

    if (blk < 1024) {
        int e = blk * 256 + tid;
        int d = load_edge(ei, e);
        int s = load_edge(ei, E_CNT + e);
        if ((unsigned)d < BN && (unsigned)s < BN) {
            int pos = atomicAdd(&g_cnt[d], 1);
            if (pos < CAP) {
                g_bucket[d * CAP + pos] = s;
            } else {                              // exact spill path (≈never)
                int op = atomicAdd(&g_ovcnt, 1);
                if (op < E_CNT) { g_ovsrc[op] = s; g_ovdst[op] = d; }
            }
        }
        return;
    }

    int q  = blk - 1024;                 // 0..3071
    int n0 = (q & 127) * 32;             // 128 n-tiles
    int c0 = ((q >> 7) % 6) * 32;        // 6 c-tiles
    int b  = q / (128 * 6);              // 4 batches
    int tx = tid & 31, ty = tid >> 5;    // 32 x 8
    #pragma unroll
    for (int i = 0; i < 4; ++i) {
        int c = c0 + ty + 8 * i;
        tile[ty + 8 * i][tx] = x[((size_t)b * C_IN + c) * Nn + n0 + tx];
    }
    __syncthreads();
    #pragma unroll
    for (int i = 0; i < 4; ++i) {
        int n = n0 + ty + 8 * i;
        size_t idx = ((size_t)b * Nn + n) * C_IN + c0 + tx;
        float v = tile[tx][ty + 8 * i];
        g_xt[idx] = v;
        g_bx_h[idx] = __float2half_rn(v);
    }
}

// ---------------- aggregation: one warp per node, float4 gathers ----------------
__global__ void agg_kernel() {
    int gtid = blockIdx.x * blockDim.x + threadIdx.x;
    int node = gtid >> 5;
    int lane = threadIdx.x & 31;
    if (node >= BN) return;
    int deg = g_cnt[node];
    int nb  = deg < CAP ? deg : CAP;
    bool lo16 = lane < 16;

    const float4 NEG4 = make_float4(-CUDART_INF_F, -CUDART_INF_F, -CUDART_INF_F, -CUDART_INF_F);
    float4 ma = NEG4, mb = NEG4;

    const int* brow = g_bucket + node * CAP;
    int my_src = (lane < nb) ? brow[lane] : 0;
    int cnt = nb < 32 ? nb : 32;

    int i = 0;
    for (; i + 4 <= cnt; i += 4) {       // 4 neighbors in flight, float4-wide
        int s0 = __shfl_sync(0xFFFFFFFFu, my_src, i);
        int s1 = __shfl_sync(0xFFFFFFFFu, my_src, i + 1);
        int s2 = __shfl_sync(0xFFFFFFFFu, my_src, i + 2);
        int s3 = __shfl_sync(0xFFFFFFFFu, my_src, i + 3);
        const float4* r0 = (const float4*)(g_xt + (size_t)s0 * C_IN);
        const float4* r1 = (const float4*)(g_xt + (size_t)s1 * C_IN);
        const float4* r2 = (const float4*)(g_xt + (size_t)s2 * C_IN);
        const float4* r3 = (const float4*)(g_xt + (size_t)s3 * C_IN);
        float4 a0 = r0[lane], a1 = r1[lane], a2 = r2[lane], a3 = r3[lane];
        if (lo16) {
            float4 b0 = r0[32 + lane], b1 = r1[32 + lane];
            float4 b2 = r2[32 + lane], b3 = r3[32 + lane];
            mb = max4(mb, max4(max4(b0, b1), max4(b2, b3)));
        }
        ma = max4(ma, max4(max4(a0, a1), max4(a2, a3)));
    }
    for (; i < cnt; ++i) {
        int s0 = __shfl_sync(0xFFFFFFFFu, my_src, i);
        const float4* r0 = (const float4*)(g_xt + (size_t)s0 * C_IN);
        ma = max4(ma, r0[lane]);
        if (lo16) mb = max4(mb, r0[32 + lane]);
    }
    for (int e = 32; e < nb; ++e) {
        int s = brow[e];
        const float4* r = (const float4*)(g_xt + (size_t)s * C_IN);
        ma = max4(ma, r[lane]);
        if (lo16) mb = max4(mb, r[32 + lane]);
    }
    int nov = g_ovcnt;
    if (nov > E_CNT) nov = E_CNT;
    for (int e = 0; e < nov; ++e) {
        if (g_ovdst[e] == node) {
            const float4* r = (const float4*)(g_xt + (size_t)g_ovsrc[e] * C_IN);
            ma = max4(ma, r[lane]);
            if (lo16) mb = max4(mb, r[32 + lane]);
        }
    }

    const float4* xr = (const float4*)(g_xt + (size_t)node * C_IN);
    bool has = deg > 0;
    {
        float4 xa = xr[lane];
        float4 va = has ? make_float4(ma.x - xa.x, ma.y - xa.y, ma.z - xa.z, ma.w - xa.w)
                        : make_float4(0.f, 0.f, 0.f, 0.f);
        *(uint2*)((char*)g_bg_h + ((size_t)node * C_IN + lane * 4) * 2) = pack_h4(va);
    }
    if (lo16) {
        float4 xb = xr[32 + lane];
        float4 vb = has ? make_float4(mb.x - xb.x, mb.y - xb.y, mb.z - xb.z, mb.w - xb.w)
                        : make_float4(0.f, 0.f, 0.f, 0.f);
        *(uint2*)((char*)g_bg_h + ((size_t)node * C_IN + 128 + lane * 4) * 2) = pack_h4(vb);
    }
}

// ---------------- HMMA GEMM: out = relu(A @ B + bias) -------------------------
// 2-term fp16 split: D = A_hi*B + A_lo*B (fp32 reg accum). A is represented to
// ~22 bits; the only dropped contribution is A*(B - fp16(B)) ~ 2^-11 RMS.
// CTA tile 128(M) x 128(N); 8 warps = 4(M) x 2(N), warp tile 32 x 64.
// 6 K-chunks of 64 fp16; 3 smem tiles per chunk (Ah, Al, Bh) = 55296B.
// smem pitch 144B -> bank-conflict-free ldmatrix.  (Structure = R8 skeleton,
// the best-measured GEMM; only the split math and B-lo removal changed.)

#define PITCH_B 144
#define TILE_BYTES (128 * PITCH_B)     // 18432
#define OFF_AH 0
#define OFF_AL TILE_BYTES
#define OFF_BH (2 * TILE_BYTES)
#define GEMM_SMEM (3 * TILE_BYTES)     // 55296

extern __shared__ __align__(16) char g_dsm[];

__global__ __launch_bounds__(256, 2) void hmma_gemm_kernel(
    const float* __restrict__ bias, float* __restrict__ out)
{
    char* Ah = g_dsm;
    char* Al = g_dsm + OFF_AL;
    char* Bh = g_dsm + OFF_BH;

    int tid  = threadIdx.x;
    int wid  = tid >> 5;
    int lane = tid & 31;
    int wm   = wid & 3;        // warp row 0..3  -> m offset wm*32
    int wn   = wid >> 2;       // warp col 0..1  -> n offset wn*64
    int n0 = blockIdx.x * 128;
    int m0 = blockIdx.y * 128;
    int bb = blockIdx.z;

    uint32_t ah_base = smem_u32(Ah);
    uint32_t al_base = smem_u32(Al);
    uint32_t bh_base = smem_u32(Bh);

    int row_in = lane & 7;
    int sub    = lane >> 3;      // 0..3

    const char* a_hi = (const char*)g_a_hi;
    const char* a_lo = (const char*)g_a_lo;
    const char* bx_h = (const char*)g_bx_h;
    const char* bg_h = (const char*)g_bg_h;

    int node0 = bb * Nn + n0;

    float acc[2][8][4];
    #pragma unroll
    for (int i = 0; i < 2; ++i)
        #pragma unroll
        for (int j = 0; j < 8; ++j)
            #pragma unroll
            for (int r = 0; r < 4; ++r) acc[i][j][r] = 0.0f;

    for (int c6 = 0; c6 < 6; ++c6) {
        const char* b_src = (c6 < 3) ? bx_h : bg_h;
        int kkA = c6 * 64;                 // A K-offset (fp16 elements)
        int kkB = (c6 % 3) * 64;           // B K-offset within its source

        // fill 3 tiles: each thread writes 4 granules per tile
        #pragma unroll
        for (int i = 0; i < 4; ++i) {
            int idx = tid + 256 * i;       // 0..1023
            int row = idx >> 3;
            int q   = idx & 7;
            size_t a_off = (size_t)(m0 + row) * (K2 * 2) + kkA * 2 + q * 16;
            size_t b_off = (size_t)(node0 + row) * (C_IN * 2) + kkB * 2 + q * 16;
            uint32_t so = row * PITCH_B + q * 16;
            *(uint4*)(Ah + so) = *(const uint4*)(a_hi + a_off);
            *(uint4*)(Al + so) = *(const uint4*)(a_lo + a_off);
            *(uint4*)(Bh + so) = *(const uint4*)(b_src + b_off);
        }
        __syncthreads();

        #pragma unroll
        for (int ks = 0; ks < 4; ++ks) {
            int k0 = ks * 16;
            uint32_t a_row_off  = (wm * 32 + row_in + (sub & 1) * 8) * PITCH_B
                                  + (k0 + (sub >> 1) * 8) * 2;
            uint32_t b_lane_off = (wn * 64 + (sub >> 1) * 8 + row_in) * PITCH_B
                                  + (k0 + (sub & 1) * 8) * 2;

            uint32_t ah[2][4], al[2][4];
            #pragma unroll
            for (int f = 0; f < 2; ++f)
                ldsm_x4(ah_base + a_row_off + f * 16 * PITCH_B,
                        ah[f][0], ah[f][1], ah[f][2], ah[f][3]);

            uint32_t bh[8][2];
            #pragma unroll
            for (int j = 0; j < 4; ++j) {
                uint32_t r0, r1, r2, r3;
                ldsm_x4(bh_base + b_lane_off + j * 16 * PITCH_B, r0, r1, r2, r3);
                bh[j * 2][0] = r0; bh[j * 2][1] = r1;
                bh[j * 2 + 1][0] = r2; bh[j * 2 + 1][1] = r3;
            }
            // hi * B
            #pragma unroll
            for (int mi = 0; mi < 2; ++mi)
                #pragma unroll
                for (int nj = 0; nj < 8; ++nj)
                    mma_f16(acc[mi][nj][0], acc[mi][nj][1], acc[mi][nj][2], acc[mi][nj][3],
                            ah[mi][0], ah[mi][1], ah[mi][2], ah[mi][3],
                            bh[nj][0], bh[nj][1]);
            // lo * B
            #pragma unroll
            for (int f = 0; f < 2; ++f)
                ldsm_x4(al_base + a_row_off + f * 16 * PITCH_B,
                        al[f][0], al[f][1], al[f][2], al[f][3]);
            #pragma unroll
            for (int mi = 0; mi < 2; ++mi)
                #pragma unroll
                for (int nj = 0; nj < 8; ++nj)
                    mma_f16(acc[mi][nj][0], acc[mi][nj][1], acc[mi][nj][2], acc[mi][nj][3],
                            al[mi][0], al[mi][1], al[mi][2], al[mi][3],
                            bh[nj][0], bh[nj][1]);
        }
        __syncthreads();
    }

    // epilogue: bias + relu
    int g  = lane >> 2;        // 0..7
    int tq = lane & 3;         // 0..3
    #pragma unroll
    for (int mi = 0; mi < 2; ++mi) {
        int r0 = m0 + wm * 32 + mi * 16 + g;
        int r1 = r0 + 8;
        float bv0 = bias[r0];
        float bv1 = bias[r1];
        float* o0 = out + ((size_t)bb * C_OUT + r0) * Nn + n0 + wn * 64 + tq * 2;
        float* o1 = out + ((size_t)bb * C_OUT + r1) * Nn + n0 + wn * 64 + tq * 2;
        #pragma unroll
        for (int nj = 0; nj < 8; ++nj) {
            float2 v0, v1;
            v0.x = fmaxf(acc[mi][nj][0] + bv0, 0.0f);
            v0.y = fmaxf(acc[mi][nj][1] + bv0, 0.0f);
            v1.x = fmaxf(acc[mi][nj][2] + bv1, 0.0f);
            v1.y = fmaxf(acc[mi][nj][3] + bv1, 0.0f);
            *(float2*)(o0 + nj * 8) = v0;
            *(float2*)(o1 + nj * 8) = v1;
        }
    }
}

// ---------------- launcher ----------------
extern "C" void kernel_launch(void* const* d_in, const int* in_sizes, int n_in,
                              void* d_out, int out_size) {
    const float* x  = (const float*)d_in[0];       // (4,192,4096,1)
    const void*  ei = (const void*)d_in[1];        // (2, 262144) int32 or int64
    const float* W  = (const float*)d_in[2];       // (384, 384)
    const float* bv = (const float*)d_in[3];       // (384,)
    float* out = (float*)d_out;                    // (4,384,4096,1)

    cudaFuncSetAttribute(hmma_gemm_kernel,
                         cudaFuncAttributeMaxDynamicSharedMemorySize, GEMM_SMEM);

    prep_kernel<<<641, 256>>>(ei, W);                                   // 1
    transpose_scatter_kernel<<<4096, 256>>>(x, ei);                     // 2
    agg_kernel<<<(BN * 32) / 256, 256>>>();                             // 3
    hmma_gemm_kernel<<<dim3(Nn / 128, C_OUT / 128, Bz), 256, GEMM_SMEM>>>(bv, out); // 4
}